// round 8
// baseline (speedup 1.0000x reference)
#include <cuda_runtime.h>
#include <cuda_fp16.h>
#include <mma.h>
#include <math.h>

using namespace nvcuda;

#define N_NODES   50000
#define N_PAD     50048
#define N_EDGES   800000
#define HIDDEN    128
#define NUM_GRAPHS 256
#define GPAD      136
#define SCAN_BLKS 196            // ceil(50000/256)

// ---------------- scratch (device globals) ----------------------------------
__device__ float  g_h[N_NODES * HIDDEN];
__device__ float  g_agg[N_NODES * HIDDEN];
__device__ __half g_hhi[N_NODES * HIDDEN];
__device__ __half g_hlo[N_NODES * HIDDEN];
__device__ __half g_A[(size_t)N_PAD * 512];
__device__ __half g_Whi[128 * 512];
__device__ __half g_Wlo[128 * 512];
__device__ __half g_WT[256 * 32];
__device__ float  g_gsum[NUM_GRAPHS * HIDDEN];
__device__ float  g_gcnt[NUM_GRAPHS];
// edge sort
__device__ int    g_cnt[N_NODES];        // histogram, then cursor
__device__ int    g_off[N_NODES];
__device__ int    g_blk[256];
__device__ int    g_perm[N_EDGES];
__device__ int    g_sdst[N_EDGES];
__device__ int    g_ssrc[N_EDGES];
__device__ float  g_seattr[(size_t)N_EDGES * 32];   // 102.4 MB

// ---------------- helpers ------------------------------------------------------
__device__ __forceinline__ void red_v4(float* p, float a, float b, float c, float d) {
    asm volatile("red.global.add.v4.f32 [%0], {%1,%2,%3,%4};"
                 :: "l"(p), "f"(a), "f"(b), "f"(c), "f"(d) : "memory");
}
__device__ __forceinline__ float tanh_fast(float x) {
    float r; asm("tanh.approx.f32 %0, %1;" : "=f"(r) : "f"(x)); return r;
}
__device__ __forceinline__ unsigned smaddr(const void* p) {
    return (unsigned)__cvta_generic_to_shared(p);
}
#define CP16(dst, src) asm volatile("cp.async.cg.shared.global [%0], [%1], 16;" :: "r"(dst), "l"(src))
#define CP_COMMIT()    asm volatile("cp.async.commit_group;" ::: "memory")
#define CP_WAIT0()     asm volatile("cp.async.wait_group 0;" ::: "memory")

// ---------------- edge sort: histogram / scan / scatter / reorder -------------
__global__ __launch_bounds__(256) void hist_kernel(const int* __restrict__ dst) {
    int e = blockIdx.x * 256 + threadIdx.x;
    atomicAdd(&g_cnt[dst[e]], 1);
}
__global__ __launch_bounds__(256) void scan1_kernel() {
    __shared__ int s[256];
    int i = blockIdx.x * 256 + threadIdx.x;
    int v = (i < N_NODES) ? g_cnt[i] : 0;
    s[threadIdx.x] = v; __syncthreads();
#pragma unroll
    for (int o = 1; o < 256; o <<= 1) {
        int t = (threadIdx.x >= o) ? s[threadIdx.x - o] : 0;
        __syncthreads();
        s[threadIdx.x] += t;
        __syncthreads();
    }
    if (i < N_NODES) g_off[i] = s[threadIdx.x] - v;      // exclusive
    if (threadIdx.x == 255) g_blk[blockIdx.x] = s[255];
}
__global__ __launch_bounds__(256) void scan2_kernel() {
    __shared__ int s[256];
    int v = (threadIdx.x < SCAN_BLKS) ? g_blk[threadIdx.x] : 0;
    s[threadIdx.x] = v; __syncthreads();
#pragma unroll
    for (int o = 1; o < 256; o <<= 1) {
        int t = (threadIdx.x >= o) ? s[threadIdx.x - o] : 0;
        __syncthreads();
        s[threadIdx.x] += t;
        __syncthreads();
    }
    g_blk[threadIdx.x] = s[threadIdx.x] - v;             // exclusive
}
__global__ __launch_bounds__(256) void scan3_kernel() {
    int i = blockIdx.x * 256 + threadIdx.x;
    if (i < N_NODES) {
        int o = g_off[i] + g_blk[blockIdx.x];
        g_off[i] = o;
        g_cnt[i] = o;                                    // cursor for scatter
    }
}
__global__ __launch_bounds__(256) void scatter_kernel(
    const int* __restrict__ dst, const int* __restrict__ src) {
    int e = blockIdx.x * 256 + threadIdx.x;
    int d = dst[e];
    int slot = atomicAdd(&g_cnt[d], 1);
    g_sdst[slot] = d;
    g_ssrc[slot] = src[e];
    g_perm[slot] = e;
}
__global__ __launch_bounds__(256) void reorder_kernel(const float4* __restrict__ eattr) {
    int gi = blockIdx.x * 256 + threadIdx.x;     // 6.4M
    int s = gi >> 3, q = gi & 7;
    int e = g_perm[s];
    ((float4*)g_seattr)[(size_t)s * 8 + q] = eattr[(size_t)e * 8 + q];
}

// ---------------- conv1: CGConv(C=3, edge=32) -------------------------------
__global__ __launch_bounds__(256) void conv1_kernel(
    const float* __restrict__ x, const int* __restrict__ src, const int* __restrict__ dst,
    const float* __restrict__ eattr,
    const float* __restrict__ Wf, const float* __restrict__ bf,
    const float* __restrict__ Ws, const float* __restrict__ bs,
    float* __restrict__ agg)
{
    __shared__ float wf[38 * 3], ws[38 * 3], bfs[3], bss[3];
    int tid = threadIdx.x;
    if (tid < 114) { wf[tid] = Wf[tid]; ws[tid] = Ws[tid]; }
    if (tid < 3)   { bfs[tid] = bf[tid]; bss[tid] = bs[tid]; }
    __syncthreads();

    int e = blockIdx.x * 256 + tid;
    int d  = dst[e];
    int sn = src[e];

    float f[3], s[3];
#pragma unroll
    for (int j = 0; j < 3; j++) { f[j] = bfs[j]; s[j] = bss[j]; }

#pragma unroll
    for (int i = 0; i < 3; i++) {
        float xd = x[d * 3 + i];
        float xs = x[sn * 3 + i];
#pragma unroll
        for (int j = 0; j < 3; j++) {
            f[j] += xd * wf[i * 3 + j];
            s[j] += xd * ws[i * 3 + j];
            f[j] += xs * wf[(3 + i) * 3 + j];
            s[j] += xs * ws[(3 + i) * 3 + j];
        }
    }
    const float4* ep = (const float4*)(eattr + (size_t)e * 32);
#pragma unroll
    for (int q = 0; q < 8; q++) {
        float4 v = ep[q];
        float ev[4] = {v.x, v.y, v.z, v.w};
#pragma unroll
        for (int r = 0; r < 4; r++) {
            int k = 6 + q * 4 + r;
#pragma unroll
            for (int j = 0; j < 3; j++) {
                f[j] += ev[r] * wf[k * 3 + j];
                s[j] += ev[r] * ws[k * 3 + j];
            }
        }
    }
#pragma unroll
    for (int j = 0; j < 3; j++) {
        float sg = 0.5f + 0.5f * tanh_fast(0.5f * f[j]);
        float sp = fmaxf(s[j], 0.f) + __logf(1.f + __expf(-fabsf(s[j])));
        atomicAdd(agg + (size_t)d * 3 + j, sg * sp);
    }
}

// ---------------- node projection (+ fused fp16 split) ------------------------
__global__ __launch_bounds__(256) void proj_kernel(
    const float* __restrict__ x, const float* __restrict__ agg1,
    const float* __restrict__ Wp, const float* __restrict__ bp,
    float* __restrict__ h, __half* __restrict__ hhi, __half* __restrict__ hlo)
{
    int idx = blockIdx.x * 256 + threadIdx.x;
    int n = idx >> 7, c = idx & 127;
    float v = bp[c];
#pragma unroll
    for (int i = 0; i < 3; i++)
        v += (x[n * 3 + i] + agg1[n * 3 + i]) * Wp[i * 128 + c];
    v = fmaxf(v, 0.f);
    h[idx] = v;
    __half hi = __float2half(v);
    hhi[idx] = hi;
    hlo[idx] = __float2half(v - __half2float(hi));
}

// ---------------- weight pack: split Whi/Wlo [128][512], WT fp16 [256][32] ---
__global__ __launch_bounds__(256) void pack_kernel(
    const float* __restrict__ Wf, const float* __restrict__ Ws,
    __half* __restrict__ Whi, __half* __restrict__ Wlo, __half* __restrict__ WT)
{
    int idx = blockIdx.x * 256 + threadIdx.x;
    {
        int k = idx >> 9;
        int j = idx & 511;
        int role = j >> 8;
        int c = (j & 255) >> 1;
        int gate = j & 1;
        const float* G = gate ? Ws : Wf;
        float v = G[(role * 128 + k) * 128 + c];
        __half hi = __float2half(v);
        Whi[idx] = hi;
        Wlo[idx] = __float2half(v - __half2float(hi));
    }
    if (idx < 256 * 32) {
        int g = idx >> 5;
        int k = idx & 31;
        int c = g >> 1;
        int gate = g & 1;
        const float* G = gate ? Ws : Wf;
        WT[idx] = __float2half(G[(256 + k) * 128 + c]);
    }
}

// ---------------- node GEMM via split-fp16 wmma ------------------------------
__global__ __launch_bounds__(512) void gemm_node(
    const __half* __restrict__ Hhi, const __half* __restrict__ Hlo,
    const __half* __restrict__ Whi, const __half* __restrict__ Wlo,
    __half* __restrict__ A)
{
    extern __shared__ __half sm[];
    __half (*hh)[GPAD] = (__half(*)[GPAD])sm;
    __half (*hl)[GPAD] = hh + 128;
    __half (*wh)[GPAD] = hl + 128;
    __half (*wl)[GPAD] = wh + 128;

    int tid = threadIdx.x;
    int bm = blockIdx.x * 128;
    int bn = blockIdx.y * 128;

#pragma unroll
    for (int t = 0; t < 4; t++) {
        int li = tid + t * 512;
        int row = li >> 4, q = li & 15;
        int rg = bm + row; if (rg > N_NODES - 1) rg = N_NODES - 1;
        CP16(smaddr(&hh[row][q * 8]), Hhi + (size_t)rg * 128 + q * 8);
        CP16(smaddr(&hl[row][q * 8]), Hlo + (size_t)rg * 128 + q * 8);
        CP16(smaddr(&wh[row][q * 8]), Whi + (size_t)row * 512 + bn + q * 8);
        CP16(smaddr(&wl[row][q * 8]), Wlo + (size_t)row * 512 + bn + q * 8);
    }
    CP_COMMIT();
    CP_WAIT0();
    __syncthreads();

    int w  = tid >> 5;
    int mw = w & 7;
    int nh = w >> 3;
    int m0 = mw * 16;

#pragma unroll
    for (int t = 0; t < 4; t++) {
        int n0 = (nh * 4 + t) * 16;
        wmma::fragment<wmma::accumulator, 16, 16, 16, float> acc;
        wmma::fill_fragment(acc, 0.f);
#pragma unroll
        for (int k = 0; k < 8; k++) {
            wmma::fragment<wmma::matrix_a, 16, 16, 16, __half, wmma::row_major> ah, al;
            wmma::fragment<wmma::matrix_b, 16, 16, 16, __half, wmma::row_major> bh, bl;
            wmma::load_matrix_sync(ah, &hh[m0][k * 16], GPAD);
            wmma::load_matrix_sync(al, &hl[m0][k * 16], GPAD);
            wmma::load_matrix_sync(bh, &wh[k * 16][n0], GPAD);
            wmma::load_matrix_sync(bl, &wl[k * 16][n0], GPAD);
            wmma::mma_sync(acc, ah, bh, acc);
            wmma::mma_sync(acc, ah, bl, acc);
            wmma::mma_sync(acc, al, bh, acc);
        }
        wmma::fragment<wmma::accumulator, 16, 16, 16, __half> hacc;
#pragma unroll
        for (int i = 0; i < acc.num_elements; i++) hacc.x[i] = __float2half(acc.x[i]);
        wmma::store_matrix_sync(A + (size_t)(bm + m0) * 512 + bn + n0,
                                hacc, 512, wmma::mem_row_major);
    }
}

// ---------------- fused CGConv edge kernel (sorted edges, run-combined RED) ---
__global__ __launch_bounds__(256) void edge_kernel(
    const int* __restrict__ sdst, const int* __restrict__ ssrc,
    const float* __restrict__ seattr,
    const __half* __restrict__ WT,
    const float* __restrict__ bf, const float* __restrict__ bs,
    const uint4* __restrict__ A4, float* __restrict__ agg)
{
    extern __shared__ char smc[];
    __half (*Es)[32]   = (__half(*)[32])smc;                        // 4 KB
    __half (*WTs)[32]  = (__half(*)[32])(smc + 4096);               // 16 KB
    __half (*Ew)[256]  = (__half(*)[256])(smc + 4096 + 16384);      // 32 KB
    int2*  di          = (int2*)(smc + 4096 + 16384 + 32768);       // 512 B

    int tid = threadIdx.x;
    int w   = tid >> 5;
    int l   = tid & 31;
    int ebase = blockIdx.x * 64;

    if (tid < 64) di[tid] = make_int2(sdst[ebase + tid], ssrc[ebase + tid]);
    {   // sorted edge attrs (streaming)
        const float4* b4 = (const float4*)(seattr + (size_t)ebase * 32);
#pragma unroll
        for (int t = 0; t < 2; t++) {
            int li = tid + t * 256;
            float4 v = __ldcs(b4 + li);
            int e = li >> 3, q = li & 7;
            __half2* dp = (__half2*)&Es[e][q * 4];
            dp[0] = __floats2half2_rn(v.x, v.y);
            dp[1] = __floats2half2_rn(v.z, v.w);
        }
    }
    {   // gate weights
        const uint4* wsrc = (const uint4*)WT;
        uint4* wdst = (uint4*)WTs;
#pragma unroll
        for (int t = 0; t < 4; t++)
            wdst[tid + t * 256] = wsrc[tid + t * 256];
    }
    __syncthreads();

    // phase 1: Ew[64][256] = Es @ WT^T  (wmma, fp32 accum)
    {
        int mt = w & 3;
        int nb = (w >> 2) * 8;
        wmma::fragment<wmma::matrix_a, 16, 16, 16, __half, wmma::row_major> a0, a1;
        wmma::load_matrix_sync(a0, &Es[mt * 16][0], 32);
        wmma::load_matrix_sync(a1, &Es[mt * 16][16], 32);
#pragma unroll
        for (int t = 0; t < 8; t++) {
            int nt = nb + t;
            wmma::fragment<wmma::accumulator, 16, 16, 16, float> acc;
            wmma::fill_fragment(acc, 0.f);
            wmma::fragment<wmma::matrix_b, 16, 16, 16, __half, wmma::col_major> b0, b1;
            wmma::load_matrix_sync(b0, &WTs[nt * 16][0], 32);
            wmma::load_matrix_sync(b1, &WTs[nt * 16][16], 32);
            wmma::mma_sync(acc, a0, b0, acc);
            wmma::mma_sync(acc, a1, b1, acc);
            wmma::fragment<wmma::accumulator, 16, 16, 16, __half> hacc;
#pragma unroll
            for (int i = 0; i < acc.num_elements; i++) hacc.x[i] = __float2half(acc.x[i]);
            wmma::store_matrix_sync(&Ew[mt * 16][nt * 16], hacc, 256, wmma::mem_row_major);
        }
    }
    __syncthreads();

    // phase 2: warp-per-edge over 8 sorted edges; combine runs of equal dst
    float4 bf4 = *(const float4*)(bf + 4 * l);
    float4 bs4 = *(const float4*)(bs + 4 * l);
    int e0 = w * 8;

    uint4 pd[4], ps[4];
#pragma unroll
    for (int i = 0; i < 4; i++) {
        int2 ds = di[e0 + i];
        pd[i] = __ldg(A4 + (size_t)ds.x * 64 + l);
        ps[i] = __ldg(A4 + (size_t)ds.y * 64 + 32 + l);
    }

    int   cur = di[e0].x;
    float a0 = 0.f, a1 = 0.f, a2 = 0.f, a3 = 0.f;

#pragma unroll
    for (int i = 0; i < 8; i++) {
        int b = i & 3;
        int dcur = di[e0 + i].x;
        uint4 rd = pd[b], rs = ps[b];
        if (i < 4) {
            int2 ds = di[e0 + i + 4];
            pd[b] = __ldg(A4 + (size_t)ds.x * 64 + l);
            ps[b] = __ldg(A4 + (size_t)ds.y * 64 + 32 + l);
        }
        uint4 ewv = *(uint4*)&Ew[e0 + i][8 * l];
        const __half2* hd  = (const __half2*)&rd;
        const __half2* hsv = (const __half2*)&rs;
        const __half2* he  = (const __half2*)&ewv;
        const float* bfp = (const float*)&bf4;
        const float* bsp = (const float*)&bs4;
        float msg[4];
#pragma unroll
        for (int j = 0; j < 4; j++) {
            float2 fd = __half22float2(hd[j]);
            float2 fv = __half22float2(hsv[j]);
            float2 fe = __half22float2(he[j]);
            float f = bfp[j] + fd.x + fv.x + fe.x;
            float s = bsp[j] + fd.y + fv.y + fe.y;
            float sg = 0.5f + 0.5f * tanh_fast(0.5f * f);
            float sp = fmaxf(s, 0.f) + __logf(1.f + __expf(-fabsf(s)));
            msg[j] = sg * sp;
        }
        if (dcur != cur) {
            red_v4(agg + (size_t)cur * 128 + 4 * l, a0, a1, a2, a3);
            cur = dcur;
            a0 = msg[0]; a1 = msg[1]; a2 = msg[2]; a3 = msg[3];
        } else {
            a0 += msg[0]; a1 += msg[1]; a2 += msg[2]; a3 += msg[3];
        }
    }
    red_v4(agg + (size_t)cur * 128 + 4 * l, a0, a1, a2, a3);
}

// ---------------- h = relu(h + agg) + fused fp16 split ------------------------
__global__ __launch_bounds__(256) void relu_add_kernel(
    float4* __restrict__ h, const float4* __restrict__ agg,
    __half2* __restrict__ hhi, __half2* __restrict__ hlo)
{
    int idx = blockIdx.x * 256 + threadIdx.x;
    float4 a = h[idx], b = agg[idx];
    a.x = fmaxf(a.x + b.x, 0.f);
    a.y = fmaxf(a.y + b.y, 0.f);
    a.z = fmaxf(a.z + b.z, 0.f);
    a.w = fmaxf(a.w + b.w, 0.f);
    h[idx] = a;
    __half hx = __float2half(a.x), hy = __float2half(a.y);
    __half hz = __float2half(a.z), hw = __float2half(a.w);
    hhi[idx * 2 + 0] = __halves2half2(hx, hy);
    hhi[idx * 2 + 1] = __halves2half2(hz, hw);
    hlo[idx * 2 + 0] = __halves2half2(__float2half(a.x - __half2float(hx)),
                                      __float2half(a.y - __half2float(hy)));
    hlo[idx * 2 + 1] = __halves2half2(__float2half(a.z - __half2float(hz)),
                                      __float2half(a.w - __half2float(hw)));
}

// ---------------- final relu + mean pool fused (vector RED) -------------------
__global__ __launch_bounds__(256) void relu_pool_kernel(
    const float4* __restrict__ h, const float4* __restrict__ agg,
    const int* __restrict__ batch,
    float* __restrict__ gsum, float* __restrict__ gcnt)
{
    int idx = blockIdx.x * 256 + threadIdx.x;
    int n = idx >> 5, q = idx & 31;
    float4 a = h[idx], b = agg[idx];
    a.x = fmaxf(a.x + b.x, 0.f);
    a.y = fmaxf(a.y + b.y, 0.f);
    a.z = fmaxf(a.z + b.z, 0.f);
    a.w = fmaxf(a.w + b.w, 0.f);
    int g = batch[n];
    red_v4(gsum + (size_t)g * 128 + 4 * q, a.x, a.y, a.z, a.w);
    if (q == 0) atomicAdd(gcnt + g, 1.f);
}

// ---------------- final MLP ---------------------------------------------------
__global__ __launch_bounds__(128) void final_kernel(
    const float* __restrict__ gsum, const float* __restrict__ gcnt,
    const float* __restrict__ W1, const float* __restrict__ b1,
    const float* __restrict__ Wh, const float* __restrict__ bh,
    float* __restrict__ out)
{
    __shared__ float mean[128];
    __shared__ float ga[128];
    int g = blockIdx.x;
    int c = threadIdx.x;
    float cnt = fmaxf(gcnt[g], 1.f);
    mean[c] = gsum[(size_t)g * 128 + c] / cnt;
    __syncthreads();
    float acc = b1[c];
#pragma unroll 8
    for (int k = 0; k < 128; k++)
        acc += mean[k] * W1[k * 128 + c];
    ga[c] = fmaxf(acc, 0.f);
    __syncthreads();
    if (c < 5) {
        float o = bh[c];
#pragma unroll 8
        for (int k = 0; k < 128; k++)
            o += ga[k] * Wh[c * 128 + k];
        out[g * 5 + c] = o;
    }
}

// =============================================================================
extern "C" void kernel_launch(void* const* d_in, const int* in_sizes, int n_in,
                              void* d_out, int out_size)
{
    const float* x        = (const float*)d_in[0];
    const int*   eidx     = (const int*)  d_in[1];
    const float* eattr    = (const float*)d_in[2];
    const int*   batch    = (const int*)  d_in[3];
    const float* Wf1      = (const float*)d_in[4];
    const float* bf1      = (const float*)d_in[5];
    const float* Ws1      = (const float*)d_in[6];
    const float* bs1      = (const float*)d_in[7];
    const float* Wp       = (const float*)d_in[8];
    const float* bp       = (const float*)d_in[9];
    const float* Wf_convs = (const float*)d_in[10];
    const float* bf_convs = (const float*)d_in[11];
    const float* Ws_convs = (const float*)d_in[12];
    const float* bs_convs = (const float*)d_in[13];
    const float* W1       = (const float*)d_in[14];
    const float* b1       = (const float*)d_in[15];
    const float* Wh       = (const float*)d_in[16];
    const float* bh       = (const float*)d_in[17];
    float* out = (float*)d_out;

    const int* srcp = eidx;
    const int* dstp = eidx + N_EDGES;

    float *p_h, *p_agg, *p_gsum, *p_gcnt, *p_seattr;
    __half *p_hhi, *p_hlo, *p_A, *p_Whi, *p_Wlo, *p_WT;
    int *p_cnt, *p_sdst, *p_ssrc;
    cudaGetSymbolAddress((void**)&p_h,    g_h);
    cudaGetSymbolAddress((void**)&p_agg,  g_agg);
    cudaGetSymbolAddress((void**)&p_hhi,  g_hhi);
    cudaGetSymbolAddress((void**)&p_hlo,  g_hlo);
    cudaGetSymbolAddress((void**)&p_A,    g_A);
    cudaGetSymbolAddress((void**)&p_Whi,  g_Whi);
    cudaGetSymbolAddress((void**)&p_Wlo,  g_Wlo);
    cudaGetSymbolAddress((void**)&p_WT,   g_WT);
    cudaGetSymbolAddress((void**)&p_gsum, g_gsum);
    cudaGetSymbolAddress((void**)&p_gcnt, g_gcnt);
    cudaGetSymbolAddress((void**)&p_cnt,  g_cnt);
    cudaGetSymbolAddress((void**)&p_sdst, g_sdst);
    cudaGetSymbolAddress((void**)&p_ssrc, g_ssrc);
    cudaGetSymbolAddress((void**)&p_seattr, g_seattr);

    static int smem_cfg = 0;
    if (!smem_cfg) {
        cudaFuncSetAttribute(edge_kernel, cudaFuncAttributeMaxDynamicSharedMemorySize, 54272);
        cudaFuncSetAttribute(gemm_node, cudaFuncAttributeMaxDynamicSharedMemorySize, 4 * 128 * GPAD * 2);
        smem_cfg = 1;
    }

    const int EB  = N_EDGES / 256;                    // 3125
    const int NB  = (N_NODES * HIDDEN) / 256;         // 25000
    const int NB4 = (N_NODES * HIDDEN / 4) / 256;     // 6250
    const int EB2 = N_EDGES / 64;                     // 12500

    // ---- sort edges by dst (once) ----
    cudaMemsetAsync(p_cnt, 0, N_NODES * sizeof(int));
    hist_kernel<<<EB, 256>>>(dstp);
    scan1_kernel<<<SCAN_BLKS, 256>>>();
    scan2_kernel<<<1, 256>>>();
    scan3_kernel<<<SCAN_BLKS, 256>>>();
    scatter_kernel<<<EB, 256>>>(dstp, srcp);
    reorder_kernel<<<(N_EDGES * 8) / 256, 256>>>((const float4*)eattr);

    // ---- conv1 + projection (writes h and its fp16 split) ----
    cudaMemsetAsync(p_agg, 0, (size_t)N_NODES * 3 * sizeof(float));
    conv1_kernel<<<EB, 256>>>(x, srcp, dstp, eattr, Wf1, bf1, Ws1, bs1, p_agg);
    proj_kernel<<<NB, 256>>>(x, p_agg, Wp, bp, p_h, p_hhi, p_hlo);

    cudaMemsetAsync(p_gsum, 0, (size_t)NUM_GRAPHS * HIDDEN * sizeof(float));
    cudaMemsetAsync(p_gcnt, 0, (size_t)NUM_GRAPHS * sizeof(float));

    // ---- two big CGConv layers ----
    for (int l = 0; l < 2; l++) {
        const float* Wf = Wf_convs + (size_t)l * 288 * 128;
        const float* Ws = Ws_convs + (size_t)l * 288 * 128;
        const float* bf = bf_convs + (size_t)l * 128;
        const float* bs = bs_convs + (size_t)l * 128;

        pack_kernel<<<(128 * 512) / 256, 256>>>(Wf, Ws, p_Whi, p_Wlo, p_WT);
        dim3 gg(N_PAD / 128, 4);
        gemm_node<<<gg, 512, 4 * 128 * GPAD * 2>>>(p_hhi, p_hlo, p_Whi, p_Wlo, p_A);
        cudaMemsetAsync(p_agg, 0, (size_t)N_NODES * HIDDEN * sizeof(float));
        edge_kernel<<<EB2, 256, 54272>>>(p_sdst, p_ssrc, p_seattr, p_WT, bf, bs,
                                         (const uint4*)p_A, p_agg);
        if (l == 0)
            relu_add_kernel<<<NB4, 256>>>((float4*)p_h, (const float4*)p_agg,
                                          (__half2*)p_hhi, (__half2*)p_hlo);
        else
            relu_pool_kernel<<<NB4, 256>>>((const float4*)p_h, (const float4*)p_agg,
                                           batch, p_gsum, p_gcnt);
    }

    final_kernel<<<NUM_GRAPHS, 128>>>(p_gsum, p_gcnt, W1, b1, Wh, bh, out);
}

// round 9
// speedup vs baseline: 1.0701x; 1.0701x over previous
#include <cuda_runtime.h>
#include <cuda_fp16.h>
#include <mma.h>
#include <math.h>

using namespace nvcuda;

#define N_NODES   50000
#define N_PAD     50048
#define N_EDGES   800000
#define HIDDEN    128
#define NUM_GRAPHS 256
#define GPAD      136
#define SCAN_BLKS 196            // ceil(50000/256)

// ---------------- scratch (device globals) ----------------------------------
__device__ float  g_h[N_NODES * HIDDEN];
__device__ float  g_agg[N_NODES * HIDDEN];
__device__ __half g_hhi[N_NODES * HIDDEN];
__device__ __half g_hlo[N_NODES * HIDDEN];
__device__ __half g_A[(size_t)N_PAD * 512];
__device__ __half g_Whi[128 * 512];
__device__ __half g_Wlo[128 * 512];
__device__ __half g_WT[256 * 32];
__device__ float  g_gsum[NUM_GRAPHS * HIDDEN];
__device__ float  g_gcnt[NUM_GRAPHS];
// edge sort
__device__ int    g_cnt[N_NODES];
__device__ int    g_off[N_NODES];
__device__ int    g_blk[256];
__device__ int    g_perm[N_EDGES];
__device__ int    g_sdst[N_EDGES];
__device__ int    g_ssrc[N_EDGES];

// ---------------- helpers ------------------------------------------------------
__device__ __forceinline__ void red_v4(float* p, float a, float b, float c, float d) {
    asm volatile("red.global.add.v4.f32 [%0], {%1,%2,%3,%4};"
                 :: "l"(p), "f"(a), "f"(b), "f"(c), "f"(d) : "memory");
}
__device__ __forceinline__ float tanh_fast(float x) {
    float r; asm("tanh.approx.f32 %0, %1;" : "=f"(r) : "f"(x)); return r;
}
__device__ __forceinline__ unsigned smaddr(const void* p) {
    return (unsigned)__cvta_generic_to_shared(p);
}
#define CP16(dst, src) asm volatile("cp.async.cg.shared.global [%0], [%1], 16;" :: "r"(dst), "l"(src))
#define CP_COMMIT()    asm volatile("cp.async.commit_group;" ::: "memory")
#define CP_WAIT0()     asm volatile("cp.async.wait_group 0;" ::: "memory")

// ---------------- edge sort: histogram / scan / scatter -----------------------
__global__ __launch_bounds__(256) void hist_kernel(const int* __restrict__ dst) {
    int e = blockIdx.x * 256 + threadIdx.x;
    atomicAdd(&g_cnt[dst[e]], 1);
}
__global__ __launch_bounds__(256) void scan1_kernel() {
    __shared__ int s[256];
    int i = blockIdx.x * 256 + threadIdx.x;
    int v = (i < N_NODES) ? g_cnt[i] : 0;
    s[threadIdx.x] = v; __syncthreads();
#pragma unroll
    for (int o = 1; o < 256; o <<= 1) {
        int t = (threadIdx.x >= o) ? s[threadIdx.x - o] : 0;
        __syncthreads();
        s[threadIdx.x] += t;
        __syncthreads();
    }
    if (i < N_NODES) g_off[i] = s[threadIdx.x] - v;
    if (threadIdx.x == 255) g_blk[blockIdx.x] = s[255];
}
__global__ __launch_bounds__(256) void scan2_kernel() {
    __shared__ int s[256];
    int v = (threadIdx.x < SCAN_BLKS) ? g_blk[threadIdx.x] : 0;
    s[threadIdx.x] = v; __syncthreads();
#pragma unroll
    for (int o = 1; o < 256; o <<= 1) {
        int t = (threadIdx.x >= o) ? s[threadIdx.x - o] : 0;
        __syncthreads();
        s[threadIdx.x] += t;
        __syncthreads();
    }
    g_blk[threadIdx.x] = s[threadIdx.x] - v;
}
__global__ __launch_bounds__(256) void scan3_kernel() {
    int i = blockIdx.x * 256 + threadIdx.x;
    if (i < N_NODES) {
        int o = g_off[i] + g_blk[blockIdx.x];
        g_off[i] = o;
        g_cnt[i] = o;
    }
}
__global__ __launch_bounds__(256) void scatter_kernel(
    const int* __restrict__ dst, const int* __restrict__ src) {
    int e = blockIdx.x * 256 + threadIdx.x;
    int d = dst[e];
    int slot = atomicAdd(&g_cnt[d], 1);
    g_sdst[slot] = d;
    g_ssrc[slot] = src[e];
    g_perm[slot] = e;
}

// ---------------- conv1: CGConv(C=3, edge=32) -------------------------------
__global__ __launch_bounds__(256) void conv1_kernel(
    const float* __restrict__ x, const int* __restrict__ src, const int* __restrict__ dst,
    const float* __restrict__ eattr,
    const float* __restrict__ Wf, const float* __restrict__ bf,
    const float* __restrict__ Ws, const float* __restrict__ bs,
    float* __restrict__ agg)
{
    __shared__ float wf[38 * 3], ws[38 * 3], bfs[3], bss[3];
    int tid = threadIdx.x;
    if (tid < 114) { wf[tid] = Wf[tid]; ws[tid] = Ws[tid]; }
    if (tid < 3)   { bfs[tid] = bf[tid]; bss[tid] = bs[tid]; }
    __syncthreads();

    int e = blockIdx.x * 256 + tid;
    int d  = dst[e];
    int sn = src[e];

    float f[3], s[3];
#pragma unroll
    for (int j = 0; j < 3; j++) { f[j] = bfs[j]; s[j] = bss[j]; }

#pragma unroll
    for (int i = 0; i < 3; i++) {
        float xd = x[d * 3 + i];
        float xs = x[sn * 3 + i];
#pragma unroll
        for (int j = 0; j < 3; j++) {
            f[j] += xd * wf[i * 3 + j];
            s[j] += xd * ws[i * 3 + j];
            f[j] += xs * wf[(3 + i) * 3 + j];
            s[j] += xs * ws[(3 + i) * 3 + j];
        }
    }
    const float4* ep = (const float4*)(eattr + (size_t)e * 32);
#pragma unroll
    for (int q = 0; q < 8; q++) {
        float4 v = ep[q];
        float ev[4] = {v.x, v.y, v.z, v.w};
#pragma unroll
        for (int r = 0; r < 4; r++) {
            int k = 6 + q * 4 + r;
#pragma unroll
            for (int j = 0; j < 3; j++) {
                f[j] += ev[r] * wf[k * 3 + j];
                s[j] += ev[r] * ws[k * 3 + j];
            }
        }
    }
#pragma unroll
    for (int j = 0; j < 3; j++) {
        float sg = 0.5f + 0.5f * tanh_fast(0.5f * f[j]);
        float sp = fmaxf(s[j], 0.f) + __logf(1.f + __expf(-fabsf(s[j])));
        atomicAdd(agg + (size_t)d * 3 + j, sg * sp);
    }
}

// ---------------- node projection (+ fused fp16 split) ------------------------
__global__ __launch_bounds__(256) void proj_kernel(
    const float* __restrict__ x, const float* __restrict__ agg1,
    const float* __restrict__ Wp, const float* __restrict__ bp,
    float* __restrict__ h, __half* __restrict__ hhi, __half* __restrict__ hlo)
{
    int idx = blockIdx.x * 256 + threadIdx.x;
    int n = idx >> 7, c = idx & 127;
    float v = bp[c];
#pragma unroll
    for (int i = 0; i < 3; i++)
        v += (x[n * 3 + i] + agg1[n * 3 + i]) * Wp[i * 128 + c];
    v = fmaxf(v, 0.f);
    h[idx] = v;
    __half hi = __float2half(v);
    hhi[idx] = hi;
    hlo[idx] = __float2half(v - __half2float(hi));
}

// ---------------- weight pack ---------------------------------------------------
__global__ __launch_bounds__(256) void pack_kernel(
    const float* __restrict__ Wf, const float* __restrict__ Ws,
    __half* __restrict__ Whi, __half* __restrict__ Wlo, __half* __restrict__ WT)
{
    int idx = blockIdx.x * 256 + threadIdx.x;
    {
        int k = idx >> 9;
        int j = idx & 511;
        int role = j >> 8;
        int c = (j & 255) >> 1;
        int gate = j & 1;
        const float* G = gate ? Ws : Wf;
        float v = G[(role * 128 + k) * 128 + c];
        __half hi = __float2half(v);
        Whi[idx] = hi;
        Wlo[idx] = __float2half(v - __half2float(hi));
    }
    if (idx < 256 * 32) {
        int g = idx >> 5;
        int k = idx & 31;
        int c = g >> 1;
        int gate = g & 1;
        const float* G = gate ? Ws : Wf;
        WT[idx] = __float2half(G[(256 + k) * 128 + c]);
    }
}

// ---------------- node GEMM via split-fp16 wmma ------------------------------
__global__ __launch_bounds__(512) void gemm_node(
    const __half* __restrict__ Hhi, const __half* __restrict__ Hlo,
    const __half* __restrict__ Whi, const __half* __restrict__ Wlo,
    __half* __restrict__ A)
{
    extern __shared__ __half sm[];
    __half (*hh)[GPAD] = (__half(*)[GPAD])sm;
    __half (*hl)[GPAD] = hh + 128;
    __half (*wh)[GPAD] = hl + 128;
    __half (*wl)[GPAD] = wh + 128;

    int tid = threadIdx.x;
    int bm = blockIdx.x * 128;
    int bn = blockIdx.y * 128;

#pragma unroll
    for (int t = 0; t < 4; t++) {
        int li = tid + t * 512;
        int row = li >> 4, q = li & 15;
        int rg = bm + row; if (rg > N_NODES - 1) rg = N_NODES - 1;
        CP16(smaddr(&hh[row][q * 8]), Hhi + (size_t)rg * 128 + q * 8);
        CP16(smaddr(&hl[row][q * 8]), Hlo + (size_t)rg * 128 + q * 8);
        CP16(smaddr(&wh[row][q * 8]), Whi + (size_t)row * 512 + bn + q * 8);
        CP16(smaddr(&wl[row][q * 8]), Wlo + (size_t)row * 512 + bn + q * 8);
    }
    CP_COMMIT();
    CP_WAIT0();
    __syncthreads();

    int w  = tid >> 5;
    int mw = w & 7;
    int nh = w >> 3;
    int m0 = mw * 16;

#pragma unroll
    for (int t = 0; t < 4; t++) {
        int n0 = (nh * 4 + t) * 16;
        wmma::fragment<wmma::accumulator, 16, 16, 16, float> acc;
        wmma::fill_fragment(acc, 0.f);
#pragma unroll
        for (int k = 0; k < 8; k++) {
            wmma::fragment<wmma::matrix_a, 16, 16, 16, __half, wmma::row_major> ah, al;
            wmma::fragment<wmma::matrix_b, 16, 16, 16, __half, wmma::row_major> bh, bl;
            wmma::load_matrix_sync(ah, &hh[m0][k * 16], GPAD);
            wmma::load_matrix_sync(al, &hl[m0][k * 16], GPAD);
            wmma::load_matrix_sync(bh, &wh[k * 16][n0], GPAD);
            wmma::load_matrix_sync(bl, &wl[k * 16][n0], GPAD);
            wmma::mma_sync(acc, ah, bh, acc);
            wmma::mma_sync(acc, ah, bl, acc);
            wmma::mma_sync(acc, al, bh, acc);
        }
        wmma::fragment<wmma::accumulator, 16, 16, 16, __half> hacc;
#pragma unroll
        for (int i = 0; i < acc.num_elements; i++) hacc.x[i] = __float2half(acc.x[i]);
        wmma::store_matrix_sync(A + (size_t)(bm + m0) * 512 + bn + n0,
                                hacc, 512, wmma::mem_row_major);
    }
}

// ---- fused CGConv edge kernel (sorted edges, lazy dst gather, run-combined) --
__global__ __launch_bounds__(256) void edge_kernel(
    const int* __restrict__ sdst, const int* __restrict__ ssrc,
    const int* __restrict__ perm,
    const float* __restrict__ eattr,
    const __half* __restrict__ WT,
    const float* __restrict__ bf, const float* __restrict__ bs,
    const uint4* __restrict__ A4, float* __restrict__ agg)
{
    extern __shared__ char smc[];
    __half (*Es)[32]   = (__half(*)[32])smc;                        // 4 KB
    __half (*WTs)[32]  = (__half(*)[32])(smc + 4096);               // 16 KB
    __half (*Ew)[256]  = (__half(*)[256])(smc + 4096 + 16384);      // 32 KB
    int2*  di          = (int2*)(smc + 4096 + 16384 + 32768);       // 512 B

    int tid = threadIdx.x;
    int w   = tid >> 5;
    int l   = tid & 31;
    int ebase = blockIdx.x * 64;

    if (tid < 64) di[tid] = make_int2(sdst[ebase + tid], ssrc[ebase + tid]);
    {   // edge attrs gathered via perm (each row = one aligned 128B line)
        const float4* b4 = (const float4*)eattr;
#pragma unroll
        for (int t = 0; t < 2; t++) {
            int li = tid + t * 256;          // 0..511
            int e = li >> 3, q = li & 7;
            int pe = __ldg(perm + ebase + e);
            float4 v = __ldcs(b4 + (size_t)pe * 8 + q);
            __half2* dp = (__half2*)&Es[e][q * 4];
            dp[0] = __floats2half2_rn(v.x, v.y);
            dp[1] = __floats2half2_rn(v.z, v.w);
        }
    }
    {   // gate weights
        const uint4* wsrc = (const uint4*)WT;
        uint4* wdst = (uint4*)WTs;
#pragma unroll
        for (int t = 0; t < 4; t++)
            wdst[tid + t * 256] = wsrc[tid + t * 256];
    }
    __syncthreads();

    // phase 1: Ew[64][256] = Es @ WT^T  (wmma, fp32 accum)
    {
        int mt = w & 3;
        int nb = (w >> 2) * 8;
        wmma::fragment<wmma::matrix_a, 16, 16, 16, __half, wmma::row_major> a0, a1;
        wmma::load_matrix_sync(a0, &Es[mt * 16][0], 32);
        wmma::load_matrix_sync(a1, &Es[mt * 16][16], 32);
#pragma unroll
        for (int t = 0; t < 8; t++) {
            int nt = nb + t;
            wmma::fragment<wmma::accumulator, 16, 16, 16, float> acc;
            wmma::fill_fragment(acc, 0.f);
            wmma::fragment<wmma::matrix_b, 16, 16, 16, __half, wmma::col_major> b0, b1;
            wmma::load_matrix_sync(b0, &WTs[nt * 16][0], 32);
            wmma::load_matrix_sync(b1, &WTs[nt * 16][16], 32);
            wmma::mma_sync(acc, a0, b0, acc);
            wmma::mma_sync(acc, a1, b1, acc);
            wmma::fragment<wmma::accumulator, 16, 16, 16, __half> hacc;
#pragma unroll
            for (int i = 0; i < acc.num_elements; i++) hacc.x[i] = __float2half(acc.x[i]);
            wmma::store_matrix_sync(&Ew[mt * 16][nt * 16], hacc, 256, wmma::mem_row_major);
        }
    }
    __syncthreads();

    // phase 2: warp-per-edge; dst row loaded once per run (warp-uniform branch)
    float4 bf4 = *(const float4*)(bf + 4 * l);
    float4 bs4 = *(const float4*)(bs + 4 * l);
    const float* bfp = (const float*)&bf4;
    const float* bsp = (const float*)&bs4;
    int e0 = w * 8;

    // rolling prefetch of src rows, depth 4
    uint4 ps[4];
#pragma unroll
    for (int i = 0; i < 4; i++)
        ps[i] = __ldg(A4 + (size_t)di[e0 + i].y * 64 + 32 + l);

    int cur = di[e0].x;
    uint4 rd = __ldg(A4 + (size_t)cur * 64 + l);
    float fdx[4], fdy[4];
    {
        const __half2* hd = (const __half2*)&rd;
#pragma unroll
        for (int j = 0; j < 4; j++) {
            float2 t = __half22float2(hd[j]);
            fdx[j] = t.x; fdy[j] = t.y;
        }
    }
    float facc[4] = {0.f, 0.f, 0.f, 0.f};

#pragma unroll
    for (int i = 0; i < 8; i++) {
        int b = i & 3;
        uint4 rs = ps[b];
        if (i < 4)
            ps[b] = __ldg(A4 + (size_t)di[e0 + i + 4].y * 64 + 32 + l);

        int d = di[e0 + i].x;
        if (d != cur) {                       // warp-uniform
            red_v4(agg + (size_t)cur * 128 + 4 * l, facc[0], facc[1], facc[2], facc[3]);
            cur = d;
            rd = __ldg(A4 + (size_t)cur * 64 + l);
            const __half2* hd = (const __half2*)&rd;
#pragma unroll
            for (int j = 0; j < 4; j++) {
                float2 t = __half22float2(hd[j]);
                fdx[j] = t.x; fdy[j] = t.y;
            }
#pragma unroll
            for (int j = 0; j < 4; j++) facc[j] = 0.f;
        }

        uint4 ewv = *(uint4*)&Ew[e0 + i][8 * l];
        const __half2* hsv = (const __half2*)&rs;
        const __half2* he  = (const __half2*)&ewv;
#pragma unroll
        for (int j = 0; j < 4; j++) {
            float2 fv = __half22float2(hsv[j]);
            float2 fe = __half22float2(he[j]);
            float f = bfp[j] + fdx[j] + fv.x + fe.x;
            float s = bsp[j] + fdy[j] + fv.y + fe.y;
            float sg = 0.5f + 0.5f * tanh_fast(0.5f * f);
            float sp = fmaxf(s, 0.f) + __logf(1.f + __expf(-fabsf(s)));
            facc[j] += sg * sp;
        }
    }
    red_v4(agg + (size_t)cur * 128 + 4 * l, facc[0], facc[1], facc[2], facc[3]);
}

// ---------------- h = relu(h + agg) + fused fp16 split ------------------------
__global__ __launch_bounds__(256) void relu_add_kernel(
    float4* __restrict__ h, const float4* __restrict__ agg,
    __half2* __restrict__ hhi, __half2* __restrict__ hlo)
{
    int idx = blockIdx.x * 256 + threadIdx.x;
    float4 a = h[idx], b = agg[idx];
    a.x = fmaxf(a.x + b.x, 0.f);
    a.y = fmaxf(a.y + b.y, 0.f);
    a.z = fmaxf(a.z + b.z, 0.f);
    a.w = fmaxf(a.w + b.w, 0.f);
    h[idx] = a;
    __half hx = __float2half(a.x), hy = __float2half(a.y);
    __half hz = __float2half(a.z), hw = __float2half(a.w);
    hhi[idx * 2 + 0] = __halves2half2(hx, hy);
    hhi[idx * 2 + 1] = __halves2half2(hz, hw);
    hlo[idx * 2 + 0] = __halves2half2(__float2half(a.x - __half2float(hx)),
                                      __float2half(a.y - __half2float(hy)));
    hlo[idx * 2 + 1] = __halves2half2(__float2half(a.z - __half2float(hz)),
                                      __float2half(a.w - __half2float(hw)));
}

// ---------------- final relu + mean pool fused (vector RED) -------------------
__global__ __launch_bounds__(256) void relu_pool_kernel(
    const float4* __restrict__ h, const float4* __restrict__ agg,
    const int* __restrict__ batch,
    float* __restrict__ gsum, float* __restrict__ gcnt)
{
    int idx = blockIdx.x * 256 + threadIdx.x;
    int n = idx >> 5, q = idx & 31;
    float4 a = h[idx], b = agg[idx];
    a.x = fmaxf(a.x + b.x, 0.f);
    a.y = fmaxf(a.y + b.y, 0.f);
    a.z = fmaxf(a.z + b.z, 0.f);
    a.w = fmaxf(a.w + b.w, 0.f);
    int g = batch[n];
    red_v4(gsum + (size_t)g * 128 + 4 * q, a.x, a.y, a.z, a.w);
    if (q == 0) atomicAdd(gcnt + g, 1.f);
}

// ---------------- final MLP ---------------------------------------------------
__global__ __launch_bounds__(128) void final_kernel(
    const float* __restrict__ gsum, const float* __restrict__ gcnt,
    const float* __restrict__ W1, const float* __restrict__ b1,
    const float* __restrict__ Wh, const float* __restrict__ bh,
    float* __restrict__ out)
{
    __shared__ float mean[128];
    __shared__ float ga[128];
    int g = blockIdx.x;
    int c = threadIdx.x;
    float cnt = fmaxf(gcnt[g], 1.f);
    mean[c] = gsum[(size_t)g * 128 + c] / cnt;
    __syncthreads();
    float acc = b1[c];
#pragma unroll 8
    for (int k = 0; k < 128; k++)
        acc += mean[k] * W1[k * 128 + c];
    ga[c] = fmaxf(acc, 0.f);
    __syncthreads();
    if (c < 5) {
        float o = bh[c];
#pragma unroll 8
        for (int k = 0; k < 128; k++)
            o += ga[k] * Wh[c * 128 + k];
        out[g * 5 + c] = o;
    }
}

// =============================================================================
extern "C" void kernel_launch(void* const* d_in, const int* in_sizes, int n_in,
                              void* d_out, int out_size)
{
    const float* x        = (const float*)d_in[0];
    const int*   eidx     = (const int*)  d_in[1];
    const float* eattr    = (const float*)d_in[2];
    const int*   batch    = (const int*)  d_in[3];
    const float* Wf1      = (const float*)d_in[4];
    const float* bf1      = (const float*)d_in[5];
    const float* Ws1      = (const float*)d_in[6];
    const float* bs1      = (const float*)d_in[7];
    const float* Wp       = (const float*)d_in[8];
    const float* bp       = (const float*)d_in[9];
    const float* Wf_convs = (const float*)d_in[10];
    const float* bf_convs = (const float*)d_in[11];
    const float* Ws_convs = (const float*)d_in[12];
    const float* bs_convs = (const float*)d_in[13];
    const float* W1       = (const float*)d_in[14];
    const float* b1       = (const float*)d_in[15];
    const float* Wh       = (const float*)d_in[16];
    const float* bh       = (const float*)d_in[17];
    float* out = (float*)d_out;

    const int* srcp = eidx;
    const int* dstp = eidx + N_EDGES;

    float *p_h, *p_agg, *p_gsum, *p_gcnt;
    __half *p_hhi, *p_hlo, *p_A, *p_Whi, *p_Wlo, *p_WT;
    int *p_cnt, *p_sdst, *p_ssrc, *p_perm;
    cudaGetSymbolAddress((void**)&p_h,    g_h);
    cudaGetSymbolAddress((void**)&p_agg,  g_agg);
    cudaGetSymbolAddress((void**)&p_hhi,  g_hhi);
    cudaGetSymbolAddress((void**)&p_hlo,  g_hlo);
    cudaGetSymbolAddress((void**)&p_A,    g_A);
    cudaGetSymbolAddress((void**)&p_Whi,  g_Whi);
    cudaGetSymbolAddress((void**)&p_Wlo,  g_Wlo);
    cudaGetSymbolAddress((void**)&p_WT,   g_WT);
    cudaGetSymbolAddress((void**)&p_gsum, g_gsum);
    cudaGetSymbolAddress((void**)&p_gcnt, g_gcnt);
    cudaGetSymbolAddress((void**)&p_cnt,  g_cnt);
    cudaGetSymbolAddress((void**)&p_sdst, g_sdst);
    cudaGetSymbolAddress((void**)&p_ssrc, g_ssrc);
    cudaGetSymbolAddress((void**)&p_perm, g_perm);

    static int smem_cfg = 0;
    if (!smem_cfg) {
        cudaFuncSetAttribute(edge_kernel, cudaFuncAttributeMaxDynamicSharedMemorySize, 54272);
        cudaFuncSetAttribute(gemm_node, cudaFuncAttributeMaxDynamicSharedMemorySize, 4 * 128 * GPAD * 2);
        smem_cfg = 1;
    }

    const int EB  = N_EDGES / 256;                    // 3125
    const int NB  = (N_NODES * HIDDEN) / 256;         // 25000
    const int NB4 = (N_NODES * HIDDEN / 4) / 256;     // 6250
    const int EB2 = N_EDGES / 64;                     // 12500

    // ---- sort edges by dst (once; no eattr reorder) ----
    cudaMemsetAsync(p_cnt, 0, N_NODES * sizeof(int));
    hist_kernel<<<EB, 256>>>(dstp);
    scan1_kernel<<<SCAN_BLKS, 256>>>();
    scan2_kernel<<<1, 256>>>();
    scan3_kernel<<<SCAN_BLKS, 256>>>();
    scatter_kernel<<<EB, 256>>>(dstp, srcp);

    // ---- conv1 + projection ----
    cudaMemsetAsync(p_agg, 0, (size_t)N_NODES * 3 * sizeof(float));
    conv1_kernel<<<EB, 256>>>(x, srcp, dstp, eattr, Wf1, bf1, Ws1, bs1, p_agg);
    proj_kernel<<<NB, 256>>>(x, p_agg, Wp, bp, p_h, p_hhi, p_hlo);

    cudaMemsetAsync(p_gsum, 0, (size_t)NUM_GRAPHS * HIDDEN * sizeof(float));
    cudaMemsetAsync(p_gcnt, 0, (size_t)NUM_GRAPHS * sizeof(float));

    // ---- two big CGConv layers ----
    for (int l = 0; l < 2; l++) {
        const float* Wf = Wf_convs + (size_t)l * 288 * 128;
        const float* Ws = Ws_convs + (size_t)l * 288 * 128;
        const float* bf = bf_convs + (size_t)l * 128;
        const float* bs = bs_convs + (size_t)l * 128;

        pack_kernel<<<(128 * 512) / 256, 256>>>(Wf, Ws, p_Whi, p_Wlo, p_WT);
        dim3 gg(N_PAD / 128, 4);
        gemm_node<<<gg, 512, 4 * 128 * GPAD * 2>>>(p_hhi, p_hlo, p_Whi, p_Wlo, p_A);
        cudaMemsetAsync(p_agg, 0, (size_t)N_NODES * HIDDEN * sizeof(float));
        edge_kernel<<<EB2, 256, 54272>>>(p_sdst, p_ssrc, p_perm, eattr, p_WT, bf, bs,
                                         (const uint4*)p_A, p_agg);
        if (l == 0)
            relu_add_kernel<<<NB4, 256>>>((float4*)p_h, (const float4*)p_agg,
                                          (__half2*)p_hhi, (__half2*)p_hlo);
        else
            relu_pool_kernel<<<NB4, 256>>>((const float4*)p_h, (const float4*)p_agg,
                                           batch, p_gsum, p_gcnt);
    }

    final_kernel<<<NUM_GRAPHS, 128>>>(p_gsum, p_gcnt, W1, b1, Wh, bh, out);
}